// round 8
// baseline (speedup 1.0000x reference)
#include <cuda_runtime.h>
#include <cuda_fp16.h>
#include <math.h>

#define NBATCH 4
#define NC     256
#define HW     65536
#define WIMG   256
#define NSP    1024
#define HID    128
#define ODIM   64
#define INV_T  10.0f

// ---------------- scratch (device globals; no allocation allowed) ----------------
__device__ int    g_cnti[NBATCH * NSP];
__device__ int    g_off[NBATCH * NSP];
__device__ int    g_rank[(size_t)NBATCH * HW];
__device__ unsigned char g_adj[(size_t)NBATCH * NSP * NSP];     // 4 MB
__device__ float  g_invdeg[NBATCH * NSP];
__device__ __half g_adjn[(size_t)NBATCH * NSP * NSP];           // 8 MB normalized adjacency
__device__ __half g_pp[(size_t)NBATCH * HW * HID];              // 64 MB sorted projected rows
__device__ __half g_pT[(size_t)NBATCH * HID * NSP];             // [b][j][s] fp16
__device__ __half g_h1[(size_t)NBATCH * NSP * HID];
__device__ __half g_h2[(size_t)NBATCH * NSP * HID];
__device__ __half g_w1h[HID * NC];
__device__ __half g_w2h[HID * HID];
__device__ __half g_wp1h[ODIM * HID];
__device__ __half g_wp2h[ODIM * HID];
__device__ float  g_z1[NBATCH * NSP * ODIM];
__device__ float  g_z2[NBATCH * NSP * ODIM];
__device__ float  g_diag[NBATCH * NSP];

// ---------------- mma helpers ---------------------------------------------------
__device__ __forceinline__ unsigned sptr(const void* p) {
    return (unsigned)__cvta_generic_to_shared(p);
}
__device__ __forceinline__ void ldsm4(unsigned& r0, unsigned& r1, unsigned& r2, unsigned& r3,
                                      unsigned addr) {
    asm volatile("ldmatrix.sync.aligned.m8n8.x4.shared.b16 {%0,%1,%2,%3}, [%4];"
                 : "=r"(r0), "=r"(r1), "=r"(r2), "=r"(r3) : "r"(addr));
}
__device__ __forceinline__ void mma16816(float* d, const unsigned* a, const unsigned* b) {
    asm volatile("mma.sync.aligned.m16n8k16.row.col.f32.f16.f16.f32 "
                 "{%0,%1,%2,%3}, {%4,%5,%6,%7}, {%8,%9}, {%0,%1,%2,%3};"
                 : "+f"(d[0]), "+f"(d[1]), "+f"(d[2]), "+f"(d[3])
                 : "r"(a[0]), "r"(a[1]), "r"(a[2]), "r"(a[3]), "r"(b[0]), "r"(b[1]));
}

// ---------------- zero: adj(bytes) + cnti + out --------------------------------
__global__ __launch_bounds__(256) void zero_kernel(float* d_out) {
    size_t gid = (size_t)blockIdx.x * 256 + threadIdx.x;
    ((uint2*)g_adj)[gid] = make_uint2(0u, 0u);
    if (gid < (NBATCH * NSP) / 4) ((int4*)g_cnti)[gid] = make_int4(0, 0, 0, 0);
    if (gid == 0) d_out[0] = 0.f;
}

// ---------------- counts (+rank) + binary adjacency ----------------------------
__global__ __launch_bounds__(256) void count_adj_kernel(const int* __restrict__ idx) {
    int b = blockIdx.y;
    int p = blockIdx.x * 256 + threadIdx.x;
    const int* ib = idx + (size_t)b * HW;
    int s = ib[p];
    int r = atomicAdd(&g_cnti[b * NSP + s], 1);
    g_rank[(size_t)b * HW + p] = r;
    unsigned char* adjb = g_adj + (size_t)b * NSP * NSP;
    if ((p & (WIMG - 1)) < WIMG - 1) {
        int s2 = ib[p + 1];
        if (s2 != s) { adjb[(size_t)s * NSP + s2] = 1; adjb[(size_t)s2 * NSP + s] = 1; }
    }
    if (p < HW - WIMG) {
        int s2 = ib[p + WIMG];
        if (s2 != s) { adjb[(size_t)s * NSP + s2] = 1; adjb[(size_t)s2 * NSP + s] = 1; }
    }
    if (p < NSP) adjb[(size_t)p * NSP + p] = 1;
}

// ---------------- exclusive scan of counts -> offsets --------------------------
__global__ __launch_bounds__(1024) void scan_kernel() {
    __shared__ int sm[NSP];
    int b = blockIdx.x, t = threadIdx.x;
    int v = g_cnti[b * NSP + t];
    sm[t] = v;
    __syncthreads();
    for (int o = 1; o < NSP; o <<= 1) {
        int x = (t >= o) ? sm[t - o] : 0;
        __syncthreads();
        sm[t] += x;
        __syncthreads();
    }
    g_off[b * NSP + t] = sm[t] - v;
}

// ---------------- invdeg = rsqrt(rowsum(adj)) ----------------------------------
__global__ __launch_bounds__(256) void invdeg_kernel() {
    int b = blockIdx.y;
    int row = blockIdx.x * 8 + (threadIdx.x >> 5);
    int lane = threadIdx.x & 31;
    const uint4* r = (const uint4*)(g_adj + ((size_t)b * NSP + row) * NSP);
    uint4 v1 = r[lane], v2 = r[lane + 32];
    unsigned int s = 0u;
    s = __dp4a(v1.x, 0x01010101u, s); s = __dp4a(v1.y, 0x01010101u, s);
    s = __dp4a(v1.z, 0x01010101u, s); s = __dp4a(v1.w, 0x01010101u, s);
    s = __dp4a(v2.x, 0x01010101u, s); s = __dp4a(v2.y, 0x01010101u, s);
    s = __dp4a(v2.z, 0x01010101u, s); s = __dp4a(v2.w, 0x01010101u, s);
    int si = (int)s;
    #pragma unroll
    for (int o = 16; o; o >>= 1) si += __shfl_xor_sync(0xffffffffu, si, o);
    if (lane == 0) g_invdeg[b * NSP + row] = rsqrtf(fmaxf((float)si, 1.0f));
}

// ---------------- materialize normalized adjacency as fp16 ---------------------
__global__ __launch_bounds__(256) void adjn_kernel() {
    size_t gid = (size_t)blockIdx.x * 256 + threadIdx.x;
    size_t e = gid * 4;
    int b = (int)(e >> 20);
    int i = (int)((e >> 10) & (NSP - 1));
    int j = (int)(e & (NSP - 1));
    uchar4 a = *(const uchar4*)(g_adj + e);
    float di = g_invdeg[b * NSP + i];
    const float* dj = &g_invdeg[b * NSP + j];
    __half2 h0 = __floats2half2_rn(a.x ? di * dj[0] : 0.f, a.y ? di * dj[1] : 0.f);
    __half2 h1 = __floats2half2_rn(a.z ? di * dj[2] : 0.f, a.w ? di * dj[3] : 0.f);
    uint2 st;
    st.x = *(unsigned*)&h0; st.y = *(unsigned*)&h1;
    ((uint2*)g_adjn)[gid] = st;
}

// ---------------- convert weights to fp16 --------------------------------------
__global__ __launch_bounds__(256) void cvtw_kernel(const float* __restrict__ W1,
                                                   const float* __restrict__ W2,
                                                   const float* __restrict__ Wp1,
                                                   const float* __restrict__ Wp2) {
    int t = blockIdx.x * 256 + threadIdx.x;
    if (t < 32768)      g_w1h[t] = __float2half(W1[t]);
    else if (t < 49152) g_w2h[t - 32768] = __float2half(W2[t - 32768]);
    else if (t < 57344) g_wp1h[t - 49152] = __float2half(Wp1[t - 49152]);
    else                g_wp2h[t - 57344] = __float2half(Wp2[t - 57344]);
}

// ---------------- pixproj: proj[p][j] = feat[:,p]^T @ W1^T, scattered store -----
// grid (HW/128, NBATCH), 256 threads.  M=HID(j)=128, N=128 pixels, K=NC=256
// smem layout (dynamic):
//   [0,      10240)  Aw  __half[128][40]   (W1 chunk, [j][k])
//   [10240,  20480)  Bs  __half[128][40]   (feat chunk transposed, [p][k])
//   [0,      34816)  Cs  __half[128][136]  (epilogue, aliases Aw+Bs)
//   [34816,  35328)  sl  int[128]
__global__ __launch_bounds__(256) void pixproj_kernel(const float* __restrict__ feat,
                                                      const int* __restrict__ idx) {
    extern __shared__ __align__(16) unsigned char smraw[];
    __half (*Aw)[40]  = (__half(*)[40])smraw;
    __half (*Bs)[40]  = (__half(*)[40])(smraw + 10240);
    __half (*Cs)[136] = (__half(*)[136])smraw;
    int* sl = (int*)(smraw + 34816);
    int b = blockIdx.y;
    int p0 = blockIdx.x * 128;
    int tid = threadIdx.x, w = tid >> 5, lane = tid & 31;
    int wm = (w >> 1) * 32, wn = (w & 1) * 64;
    if (tid < 128) {
        int p = p0 + tid;
        int s = idx[(size_t)b * HW + p];
        sl[tid] = g_off[b * NSP + s] + g_rank[(size_t)b * HW + p];
    }
    float acc[2][8][4];
    #pragma unroll
    for (int i = 0; i < 2; i++)
        #pragma unroll
        for (int j = 0; j < 8; j++)
            #pragma unroll
            for (int q = 0; q < 4; q++) acc[i][j][q] = 0.f;

    int r8 = lane & 7, grp = lane >> 3;
    for (int k0 = 0; k0 < NC; k0 += 32) {
        // stage W1 chunk [128 j][32 k]: 2 threads/row, 16 halves each (2x uint4)
        {
            int rr = tid >> 1, oo = (tid & 1) * 16;
            const __half* pa = g_w1h + (size_t)rr * NC + k0 + oo;
            *(uint4*)&Aw[rr][oo]     = *(const uint4*)pa;
            *(uint4*)&Aw[rr][oo + 8] = *(const uint4*)(pa + 8);
        }
        // stage feat chunk transposed: [32 k][128 p] fp32 -> Bs[p][k] fp16
        {
            int rr = tid >> 3, pp = (tid & 7) * 16;
            const float* src = feat + ((size_t)(b * NC + k0 + rr)) * HW + p0 + pp;
            #pragma unroll
            for (int q = 0; q < 4; q++) {
                float4 f = *(const float4*)(src + q * 4);
                Bs[pp + q * 4 + 0][rr] = __float2half(f.x);
                Bs[pp + q * 4 + 1][rr] = __float2half(f.y);
                Bs[pp + q * 4 + 2][rr] = __float2half(f.z);
                Bs[pp + q * 4 + 3][rr] = __float2half(f.w);
            }
        }
        __syncthreads();
        #pragma unroll
        for (int kk = 0; kk < 32; kk += 16) {
            unsigned af[2][4], bf[8][2];
            #pragma unroll
            for (int i = 0; i < 2; i++) {
                unsigned ad = sptr(&Aw[wm + i * 16 + r8 + ((grp & 1) << 3)][kk + ((grp & 2) << 2)]);
                ldsm4(af[i][0], af[i][1], af[i][2], af[i][3], ad);
            }
            #pragma unroll
            for (int jp = 0; jp < 4; jp++) {
                unsigned q0, q1, q2, q3;
                unsigned ad = sptr(&Bs[wn + jp * 16 + r8 + ((grp & 2) << 2)][kk + ((grp & 1) << 3)]);
                ldsm4(q0, q1, q2, q3, ad);
                bf[jp * 2][0] = q0;     bf[jp * 2][1] = q1;
                bf[jp * 2 + 1][0] = q2; bf[jp * 2 + 1][1] = q3;
            }
            #pragma unroll
            for (int i = 0; i < 2; i++)
                #pragma unroll
                for (int j = 0; j < 8; j++) mma16816(acc[i][j], af[i], bf[j]);
        }
        __syncthreads();
    }
    // stage C transposed into smem: Cs[p][j]
    {
        int rr = lane >> 2, cg = (lane & 3) * 2;
        #pragma unroll
        for (int i = 0; i < 2; i++) {
            int gm = wm + i * 16 + rr;          // j index
            #pragma unroll
            for (int j = 0; j < 8; j++) {
                int gn = wn + j * 8 + cg;       // pixel index
                Cs[gn][gm]         = __float2half(acc[i][j][0]);
                Cs[gn + 1][gm]     = __float2half(acc[i][j][1]);
                Cs[gn][gm + 8]     = __float2half(acc[i][j][2]);
                Cs[gn + 1][gm + 8] = __float2half(acc[i][j][3]);
            }
        }
    }
    __syncthreads();
    // write rows to sorted slots: 128 B per (pixel, half)
    {
        int row = tid >> 1, half = tid & 1;
        __half* dst = g_pp + ((size_t)b * HW + sl[row]) * HID + half * 64;
        const __half* src = &Cs[row][half * 64];
        #pragma unroll
        for (int q = 0; q < 8; q++)
            *(uint4*)(dst + q * 8) = *(const uint4*)(src + q * 8);
    }
}

// ---------------- contiguous segment mean -> pT [b][j][s] fp16 -----------------
__global__ __launch_bounds__(64) void segsum_kernel() {
    int s = blockIdx.x, b = blockIdx.y, t = threadIdx.x;   // t: half2 column (j pair)
    int start = g_off[b * NSP + s];
    int n = g_cnti[b * NSP + s];
    const __half2* base = (const __half2*)g_pp + ((size_t)b * HW + start) * (HID / 2) + t;
    float2 a0 = make_float2(0.f, 0.f), a1 = make_float2(0.f, 0.f);
    int r = 0;
    for (; r + 2 <= n; r += 2) {
        float2 x0 = __half22float2(base[(size_t)r * (HID / 2)]);
        float2 x1 = __half22float2(base[(size_t)(r + 1) * (HID / 2)]);
        a0.x += x0.x; a0.y += x0.y; a1.x += x1.x; a1.y += x1.y;
    }
    if (r < n) {
        float2 x0 = __half22float2(base[(size_t)r * (HID / 2)]);
        a0.x += x0.x; a0.y += x0.y;
    }
    float invn = (n > 0) ? 1.f / (float)n : 0.f;
    g_pT[((size_t)b * HID + 2 * t) * NSP + s]     = __float2half((a0.x + a1.x) * invn);
    g_pT[((size_t)b * HID + 2 * t + 1) * NSP + s] = __float2half((a0.y + a1.y) * invn);
}

// ---------------- fp16 mma GEMM: C[M,N] = A(row [m][k]) @ B([n][k])^T -----------
// flags: bit0 relu, bit1 fp16-out
#define GM_BM 64
#define GM_BN 64
#define GM_BK 32
__global__ __launch_bounds__(128) void mma_gemm(
    const __half* __restrict__ A, int lda, size_t sA,
    const __half* __restrict__ B, int ldb, size_t sB,
    void* __restrict__ Cv, int ldc, size_t sC,
    int K, const float* __restrict__ bias, int flags)
{
    __shared__ __half As[GM_BM][GM_BK + 8];
    __shared__ __half Bs[GM_BN][GM_BK + 8];
    int b = blockIdx.z;
    A += (size_t)b * sA;
    B += (size_t)b * sB;
    int m0 = blockIdx.y * GM_BM, n0 = blockIdx.x * GM_BN;
    int tid = threadIdx.x, w = tid >> 5, lane = tid & 31;
    int wm = (w >> 1) * 32, wn = (w & 1) * 32;
    float acc[2][4][4];
    #pragma unroll
    for (int i = 0; i < 2; i++)
        #pragma unroll
        for (int j = 0; j < 4; j++)
            #pragma unroll
            for (int q = 0; q < 4; q++) acc[i][j][q] = 0.f;

    int r8 = lane & 7, grp = lane >> 3;
    for (int k0 = 0; k0 < K; k0 += GM_BK) {
        int rr = tid >> 1, oo = (tid & 1) * 16;
        {
            const __half* pa = A + (size_t)(m0 + rr) * lda + k0 + oo;
            *(uint4*)&As[rr][oo]     = *(const uint4*)pa;
            *(uint4*)&As[rr][oo + 8] = *(const uint4*)(pa + 8);
            const __half* pb = B + (size_t)(n0 + rr) * ldb + k0 + oo;
            *(uint4*)&Bs[rr][oo]     = *(const uint4*)pb;
            *(uint4*)&Bs[rr][oo + 8] = *(const uint4*)(pb + 8);
        }
        __syncthreads();
        #pragma unroll
        for (int kk = 0; kk < GM_BK; kk += 16) {
            unsigned af[2][4], bf[4][2];
            #pragma unroll
            for (int i = 0; i < 2; i++) {
                unsigned ad = sptr(&As[wm + i * 16 + r8 + ((grp & 1) << 3)][kk + ((grp & 2) << 2)]);
                ldsm4(af[i][0], af[i][1], af[i][2], af[i][3], ad);
            }
            #pragma unroll
            for (int jp = 0; jp < 2; jp++) {
                unsigned q0, q1, q2, q3;
                unsigned ad = sptr(&Bs[wn + jp * 16 + r8 + ((grp & 2) << 2)][kk + ((grp & 1) << 3)]);
                ldsm4(q0, q1, q2, q3, ad);
                bf[jp * 2][0] = q0;     bf[jp * 2][1] = q1;
                bf[jp * 2 + 1][0] = q2; bf[jp * 2 + 1][1] = q3;
            }
            #pragma unroll
            for (int i = 0; i < 2; i++)
                #pragma unroll
                for (int j = 0; j < 4; j++) mma16816(acc[i][j], af[i], bf[j]);
        }
        __syncthreads();
    }
    int rr = lane >> 2, cg = (lane & 3) * 2;
    #pragma unroll
    for (int i = 0; i < 2; i++) {
        int gm = m0 + wm + i * 16 + rr;
        #pragma unroll
        for (int j = 0; j < 4; j++) {
            int gn = n0 + wn + j * 8 + cg;
            float bx = bias ? bias[gn] : 0.f;
            float by = bias ? bias[gn + 1] : 0.f;
            float v0 = acc[i][j][0] + bx, v1 = acc[i][j][1] + by;
            float v2 = acc[i][j][2] + bx, v3 = acc[i][j][3] + by;
            if (flags & 1) {
                v0 = fmaxf(v0, 0.f); v1 = fmaxf(v1, 0.f);
                v2 = fmaxf(v2, 0.f); v3 = fmaxf(v3, 0.f);
            }
            if (flags & 2) {
                __half* C = (__half*)Cv + (size_t)b * sC;
                *(__half2*)(C + (size_t)gm * ldc + gn) = __floats2half2_rn(v0, v1);
                *(__half2*)(C + (size_t)(gm + 8) * ldc + gn) = __floats2half2_rn(v2, v3);
            } else {
                float* C = (float*)Cv + (size_t)b * sC;
                *(float2*)(C + (size_t)gm * ldc + gn) = make_float2(v0, v1);
                *(float2*)(C + (size_t)(gm + 8) * ldc + gn) = make_float2(v2, v3);
            }
        }
    }
}

// ---------------- row-normalize z1, z2 (in place) + diag ------------------------
__global__ __launch_bounds__(256) void norm_kernel() {
    int b = blockIdx.y;
    int row = blockIdx.x * 8 + (threadIdx.x >> 5);
    int lane = threadIdx.x & 31;
    float* z1 = g_z1 + ((size_t)b * NSP + row) * ODIM;
    float* z2 = g_z2 + ((size_t)b * NSP + row) * ODIM;
    float a0 = z1[lane], a1 = z1[lane + 32];
    float ss = a0 * a0 + a1 * a1;
    #pragma unroll
    for (int o = 16; o; o >>= 1) ss += __shfl_xor_sync(0xffffffffu, ss, o);
    float inv = rsqrtf(fmaxf(ss, 1e-30f));
    float a0n = a0 * inv, a1n = a1 * inv;
    z1[lane] = a0n; z1[lane + 32] = a1n;
    float c0 = z2[lane], c1 = z2[lane + 32];
    float ss2 = c0 * c0 + c1 * c1;
    #pragma unroll
    for (int o = 16; o; o >>= 1) ss2 += __shfl_xor_sync(0xffffffffu, ss2, o);
    float inv2 = rsqrtf(fmaxf(ss2, 1e-30f));
    float c0n = c0 * inv2, c1n = c1 * inv2;
    z2[lane] = c0n; z2[lane + 32] = c1n;
    float dd = a0n * c0n + a1n * c1n;
    #pragma unroll
    for (int o = 16; o; o >>= 1) dd += __shfl_xor_sync(0xffffffffu, dd, o);
    if (lane == 0) g_diag[b * NSP + row] = dd * INV_T;
}

// ---------------- fused sim GEMM + online logsumexp + loss ---------------------
__global__ __launch_bounds__(256) void simlse_kernel(float* __restrict__ out) {
    __shared__ float As[ODIM][36];
    __shared__ float Bs[ODIM][66];
    __shared__ float sloss[32];
    int b = blockIdx.y;
    int m0 = blockIdx.x * 32;
    int tid = threadIdx.x;
    int tx = tid & 31, ty = tid >> 5;
    const float* z1 = g_z1 + (size_t)b * NSP * ODIM;
    const float* z2 = g_z2 + (size_t)b * NSP * ODIM;
    {
        int r = tid >> 3, cg = (tid & 7) * 8;
        float4 v1 = *(const float4*)(z1 + (size_t)(m0 + r) * ODIM + cg);
        float4 v2 = *(const float4*)(z1 + (size_t)(m0 + r) * ODIM + cg + 4);
        As[cg + 0][r] = v1.x; As[cg + 1][r] = v1.y; As[cg + 2][r] = v1.z; As[cg + 3][r] = v1.w;
        As[cg + 4][r] = v2.x; As[cg + 5][r] = v2.y; As[cg + 6][r] = v2.z; As[cg + 7][r] = v2.w;
    }
    float mrun[4], srun[4];
    #pragma unroll
    for (int i = 0; i < 4; i++) { mrun[i] = -1e30f; srun[i] = 0.f; }

    for (int n0 = 0; n0 < NSP; n0 += 64) {
        __syncthreads();
        {
            int r = tid >> 2, cg = (tid & 3) * 16;
            #pragma unroll
            for (int q = 0; q < 4; q++) {
                float4 v = *(const float4*)(z2 + (size_t)(n0 + r) * ODIM + cg + q * 4);
                Bs[cg + q * 4 + 0][r] = v.x; Bs[cg + q * 4 + 1][r] = v.y;
                Bs[cg + q * 4 + 2][r] = v.z; Bs[cg + q * 4 + 3][r] = v.w;
            }
        }
        __syncthreads();
        float acc[4][2];
        #pragma unroll
        for (int i = 0; i < 4; i++) { acc[i][0] = 0.f; acc[i][1] = 0.f; }
        #pragma unroll
        for (int kk = 0; kk < ODIM; kk++) {
            float4 a = *(const float4*)&As[kk][ty * 4];
            float2 bb = *(const float2*)&Bs[kk][tx * 2];
            float ar[4] = {a.x, a.y, a.z, a.w};
            #pragma unroll
            for (int i = 0; i < 4; i++) {
                acc[i][0] += ar[i] * bb.x;
                acc[i][1] += ar[i] * bb.y;
            }
        }
        #pragma unroll
        for (int i = 0; i < 4; i++) {
            #pragma unroll
            for (int j = 0; j < 2; j++) {
                float v = acc[i][j] * INV_T;
                if (v > mrun[i]) { srun[i] = srun[i] * __expf(mrun[i] - v) + 1.f; mrun[i] = v; }
                else             { srun[i] += __expf(v - mrun[i]); }
            }
        }
    }
    #pragma unroll
    for (int i = 0; i < 4; i++) {
        float m = mrun[i], s = srun[i];
        #pragma unroll
        for (int o = 16; o; o >>= 1) {
            float m2 = __shfl_xor_sync(0xffffffffu, m, o);
            float s2 = __shfl_xor_sync(0xffffffffu, s, o);
            float mn = fmaxf(m, m2);
            s = s * __expf(m - mn) + s2 * __expf(m2 - mn);
            m = mn;
        }
        if (tx == 0) {
            int row = m0 + ty * 4 + i;
            float lse = m + logf(s);
            sloss[ty * 4 + i] = lse - g_diag[b * NSP + row];
        }
    }
    __syncthreads();
    if (tid == 0) {
        float sum = 0.f;
        #pragma unroll
        for (int i = 0; i < 32; i++) sum += sloss[i];
        atomicAdd(out, sum * (1.0f / (NBATCH * NSP)));
    }
}

// ---------------- host launcher -----------------------------------------------
static void* dvp(const void* sym) {
    void* p = nullptr;
    cudaGetSymbolAddress(&p, sym);
    return p;
}

extern "C" void kernel_launch(void* const* d_in, const int* in_sizes, int n_in,
                              void* d_out, int out_size) {
    const float* features = (const float*)d_in[0];
    const int*   spidx    = (const int*)d_in[1];
    const float* W1  = (const float*)d_in[2];
    const float* b1  = (const float*)d_in[3];
    const float* W2  = (const float*)d_in[4];
    const float* b2  = (const float*)d_in[5];
    const float* Wp1 = (const float*)d_in[6];
    const float* bp1 = (const float*)d_in[7];
    const float* Wp2 = (const float*)d_in[8];
    const float* bp2 = (const float*)d_in[9];
    float* out = (float*)d_out;

    __half* p_adjn = (__half*)dvp(g_adjn);
    __half* p_pT   = (__half*)dvp(g_pT);
    __half* p_h1   = (__half*)dvp(g_h1);
    __half* p_h2   = (__half*)dvp(g_h2);
    __half* p_w2h  = (__half*)dvp(g_w2h);
    __half* p_wp1h = (__half*)dvp(g_wp1h);
    __half* p_wp2h = (__half*)dvp(g_wp2h);
    float*  p_z1   = (float*)dvp(g_z1);
    float*  p_z2   = (float*)dvp(g_z2);

    zero_kernel<<<2048, 256>>>(out);
    count_adj_kernel<<<dim3(HW / 256, NBATCH), 256>>>(spidx);
    scan_kernel<<<NBATCH, 1024>>>();
    invdeg_kernel<<<dim3(NSP / 8, NBATCH), 256>>>();
    adjn_kernel<<<4096, 256>>>();
    cvtw_kernel<<<256, 256>>>(W1, W2, Wp1, Wp2);
    // pixel projection with fused scatter
    const int PP_SMEM = 35328;
    pixproj_kernel<<<dim3(HW / 128, NBATCH), 256, PP_SMEM>>>(features, spidx);
    // segment mean -> pT [b][j][s]
    segsum_kernel<<<dim3(NSP, NBATCH), 64>>>();
    // gemm2: h1 = relu(adjn @ pT^T + b1)   M=1024 N=128 K=1024, fp16 out
    mma_gemm<<<dim3(HID / GM_BN, NSP / GM_BM, NBATCH), 128>>>(
        p_adjn, NSP, (size_t)NSP * NSP,
        p_pT, NSP, (size_t)HID * NSP,
        p_h1, HID, (size_t)NSP * HID,
        NSP, b1, 3);
    // gemm3: h2 = relu(h1 @ W2^T + b2)
    mma_gemm<<<dim3(HID / GM_BN, NSP / GM_BM, NBATCH), 128>>>(
        p_h1, HID, (size_t)NSP * HID,
        p_w2h, HID, 0,
        p_h2, HID, (size_t)NSP * HID,
        HID, b2, 3);
    // gemm4: z = h2 @ Wp^T + bp (fp32 out)
    mma_gemm<<<dim3(ODIM / GM_BN, NSP / GM_BM, NBATCH), 128>>>(
        p_h2, HID, (size_t)NSP * HID,
        p_wp1h, HID, 0,
        p_z1, ODIM, (size_t)NSP * ODIM,
        HID, bp1, 0);
    mma_gemm<<<dim3(ODIM / GM_BN, NSP / GM_BM, NBATCH), 128>>>(
        p_h2, HID, (size_t)NSP * HID,
        p_wp2h, HID, 0,
        p_z2, ODIM, (size_t)NSP * ODIM,
        HID, bp2, 0);
    norm_kernel<<<dim3(NSP / 8, NBATCH), 256>>>();
    simlse_kernel<<<dim3(NSP / 32, NBATCH), 256>>>(out);
}

// round 9
// speedup vs baseline: 1.4356x; 1.4356x over previous
#include <cuda_runtime.h>
#include <cuda_fp16.h>
#include <math.h>

#define NBATCH 4
#define NC     256
#define HW     65536
#define WIMG   256
#define NSP    1024
#define HID    128
#define ODIM   64
#define INV_T  10.0f

// ---------------- scratch (device globals; no allocation allowed) ----------------
__device__ int    g_cnti[NBATCH * NSP];
__device__ int    g_off[NBATCH * NSP];
__device__ int    g_rank[(size_t)NBATCH * HW];
__device__ unsigned char g_adj[(size_t)NBATCH * NSP * NSP];     // 4 MB
__device__ float  g_invdeg[NBATCH * NSP];
__device__ __half g_featT16[(size_t)NBATCH * HW * NC];          // 128 MB sorted rows
__device__ __half g_spfh[(size_t)NBATCH * NSP * NC];            // [b][s][c] fp16
__device__ __half g_pT[(size_t)NBATCH * HID * NSP];             // [b][j][s] fp16
__device__ __half g_h1[(size_t)NBATCH * NSP * HID];
__device__ __half g_h2[(size_t)NBATCH * NSP * HID];
__device__ __half g_w1h[HID * NC];
__device__ __half g_w2h[HID * HID];
__device__ __half g_wp1h[ODIM * HID];
__device__ __half g_wp2h[ODIM * HID];
__device__ float  g_z1[NBATCH * NSP * ODIM];
__device__ float  g_z2[NBATCH * NSP * ODIM];
__device__ float  g_diag[NBATCH * NSP];

// ---------------- mma helpers ---------------------------------------------------
__device__ __forceinline__ unsigned sptr(const void* p) {
    return (unsigned)__cvta_generic_to_shared(p);
}
__device__ __forceinline__ void ldsm4(unsigned& r0, unsigned& r1, unsigned& r2, unsigned& r3,
                                      unsigned addr) {
    asm volatile("ldmatrix.sync.aligned.m8n8.x4.shared.b16 {%0,%1,%2,%3}, [%4];"
                 : "=r"(r0), "=r"(r1), "=r"(r2), "=r"(r3) : "r"(addr));
}
__device__ __forceinline__ void mma16816(float* d, const unsigned* a, const unsigned* b) {
    asm volatile("mma.sync.aligned.m16n8k16.row.col.f32.f16.f16.f32 "
                 "{%0,%1,%2,%3}, {%4,%5,%6,%7}, {%8,%9}, {%0,%1,%2,%3};"
                 : "+f"(d[0]), "+f"(d[1]), "+f"(d[2]), "+f"(d[3])
                 : "r"(a[0]), "r"(a[1]), "r"(a[2]), "r"(a[3]), "r"(b[0]), "r"(b[1]));
}

// ---------------- zero: adj(bytes) + cnti + out --------------------------------
__global__ __launch_bounds__(256) void zero_kernel(float* d_out) {
    size_t gid = (size_t)blockIdx.x * 256 + threadIdx.x;
    ((uint2*)g_adj)[gid] = make_uint2(0u, 0u);
    if (gid < (NBATCH * NSP) / 4) ((int4*)g_cnti)[gid] = make_int4(0, 0, 0, 0);
    if (gid == 0) d_out[0] = 0.f;
}

// ---------------- counts (+rank) + binary adjacency, 4 px/thread ---------------
__global__ __launch_bounds__(256) void count_adj_kernel(const int* __restrict__ idx) {
    int b = blockIdx.y;
    int t = blockIdx.x * 256 + threadIdx.x;      // HW/4 threads
    int p = t * 4;
    const int* ib = idx + (size_t)b * HW;
    int4 s4 = *(const int4*)(ib + p);
    int sNext = (p + 4 < HW) ? ib[p + 4] : 0;
    int4 d4 = make_int4(0, 0, 0, 0);
    if (p < HW - WIMG) d4 = *(const int4*)(ib + p + WIMG);
    int s[5] = {s4.x, s4.y, s4.z, s4.w, sNext};
    int d[4] = {d4.x, d4.y, d4.z, d4.w};
    unsigned char* adjb = g_adj + (size_t)b * NSP * NSP;
    #pragma unroll
    for (int i = 0; i < 4; i++) {
        int si = s[i];
        int r = atomicAdd(&g_cnti[b * NSP + si], 1);
        g_rank[(size_t)b * HW + p + i] = r;
        if (((p + i) & (WIMG - 1)) < WIMG - 1) {
            int s2 = s[i + 1];
            if (s2 != si) { adjb[(size_t)si * NSP + s2] = 1; adjb[(size_t)s2 * NSP + si] = 1; }
        }
        if (p + i < HW - WIMG) {
            int s2 = d[i];
            if (s2 != si) { adjb[(size_t)si * NSP + s2] = 1; adjb[(size_t)s2 * NSP + si] = 1; }
        }
    }
    if (t < NSP) adjb[(size_t)t * NSP + t] = 1;
}

// ---------------- exclusive scan of counts -> offsets --------------------------
__global__ __launch_bounds__(1024) void scan_kernel() {
    __shared__ int sm[NSP];
    int b = blockIdx.x, t = threadIdx.x;
    int v = g_cnti[b * NSP + t];
    sm[t] = v;
    __syncthreads();
    for (int o = 1; o < NSP; o <<= 1) {
        int x = (t >= o) ? sm[t - o] : 0;
        __syncthreads();
        sm[t] += x;
        __syncthreads();
    }
    g_off[b * NSP + t] = sm[t] - v;
}

// ---------------- invdeg = rsqrt(rowsum(adj)) ----------------------------------
__global__ __launch_bounds__(256) void invdeg_kernel() {
    int b = blockIdx.y;
    int row = blockIdx.x * 8 + (threadIdx.x >> 5);
    int lane = threadIdx.x & 31;
    const uint4* r = (const uint4*)(g_adj + ((size_t)b * NSP + row) * NSP);
    uint4 v1 = r[lane], v2 = r[lane + 32];
    unsigned int s = 0u;
    s = __dp4a(v1.x, 0x01010101u, s); s = __dp4a(v1.y, 0x01010101u, s);
    s = __dp4a(v1.z, 0x01010101u, s); s = __dp4a(v1.w, 0x01010101u, s);
    s = __dp4a(v2.x, 0x01010101u, s); s = __dp4a(v2.y, 0x01010101u, s);
    s = __dp4a(v2.z, 0x01010101u, s); s = __dp4a(v2.w, 0x01010101u, s);
    int si = (int)s;
    #pragma unroll
    for (int o = 16; o; o >>= 1) si += __shfl_xor_sync(0xffffffffu, si, o);
    if (lane == 0) g_invdeg[b * NSP + row] = rsqrtf(fmaxf((float)si, 1.0f));
}

// ---------------- convert weights to fp16 --------------------------------------
__global__ __launch_bounds__(256) void cvtw_kernel(const float* __restrict__ W1,
                                                   const float* __restrict__ W2,
                                                   const float* __restrict__ Wp1,
                                                   const float* __restrict__ Wp2) {
    int t = blockIdx.x * 256 + threadIdx.x;
    if (t < 32768)      g_w1h[t] = __float2half(W1[t]);
    else if (t < 49152) g_w2h[t - 32768] = __float2half(W2[t - 32768]);
    else if (t < 57344) g_wp1h[t - 49152] = __float2half(Wp1[t - 49152]);
    else                g_wp2h[t - 57344] = __float2half(Wp2[t - 57344]);
}

// ---------------- scatter-transpose: feat [C,HW] -> featT16 [b][slot][C] -------
// grid (HW/64, NC/64, NBATCH), 256 threads  (R4/R7 proven, all batches at once)
__global__ __launch_bounds__(256) void transpose_kernel(const float* __restrict__ feat,
                                                        const int* __restrict__ idx) {
    __shared__ float tile[64][65];
    __shared__ int sl[64];
    int c0 = blockIdx.y * 64, p0 = blockIdx.x * 64, b = blockIdx.z;
    int tid = threadIdx.x;
    if (tid < 64) {
        int p = p0 + tid;
        int s = idx[(size_t)b * HW + p];
        sl[tid] = g_off[b * NSP + s] + g_rank[(size_t)b * HW + p];
    }
    int px = tid & 63, cl = tid >> 6;
    const float* f = feat + ((size_t)b * NC + c0) * HW + p0;
    #pragma unroll
    for (int i = 0; i < 16; i++)
        tile[cl + i * 4][px] = f[(size_t)(cl + i * 4) * HW + px];
    __syncthreads();
    int w = tid >> 5, lane = tid & 31;
    __half2* dst = (__half2*)g_featT16 + (size_t)b * HW * (NC / 2);
    #pragma unroll
    for (int i = 0; i < 8; i++) {
        int p = w + i * 8;
        dst[(size_t)sl[p] * (NC / 2) + (c0 >> 1) + lane] =
            __floats2half2_rn(tile[lane * 2][p], tile[lane * 2 + 1][p]);
    }
}

// ---------------- contiguous segment mean -> spfh [b][s][c] fp16 ---------------
__global__ __launch_bounds__(128) void segsum_kernel() {
    int s = blockIdx.x, b = blockIdx.y, t = threadIdx.x;
    int start = g_off[b * NSP + s];
    int n = g_cnti[b * NSP + s];
    const __half2* base = (const __half2*)g_featT16 +
                          ((size_t)b * HW + start) * (NC / 2) + t;
    float2 a0 = make_float2(0.f, 0.f), a1 = make_float2(0.f, 0.f);
    int r = 0;
    for (; r + 2 <= n; r += 2) {
        float2 x0 = __half22float2(base[(size_t)r * (NC / 2)]);
        float2 x1 = __half22float2(base[(size_t)(r + 1) * (NC / 2)]);
        a0.x += x0.x; a0.y += x0.y; a1.x += x1.x; a1.y += x1.y;
    }
    if (r < n) {
        float2 x0 = __half22float2(base[(size_t)r * (NC / 2)]);
        a0.x += x0.x; a0.y += x0.y;
    }
    float invn = (n > 0) ? 1.f / (float)n : 0.f;
    ((__half2*)g_spfh)[((size_t)b * NSP + s) * (NC / 2) + t] =
        __floats2half2_rn((a0.x + a1.x) * invn, (a0.y + a1.y) * invn);
}

// ---------------- fp16 mma GEMM: C[M,N] = A(row [m][k]) @ B([n][k])^T -----------
// flags: bit0 relu, bit1 fp16-out, bit2 transposed fp16 out (C[n][m])
#define GM_BM 64
#define GM_BN 64
#define GM_BK 32
__global__ __launch_bounds__(128) void mma_gemm(
    const __half* __restrict__ A, int lda, size_t sA,
    const __half* __restrict__ B, int ldb, size_t sB,
    void* __restrict__ Cv, int ldc, size_t sC,
    int K, const float* __restrict__ bias, int flags)
{
    __shared__ __half As[GM_BM][GM_BK + 8];
    __shared__ __half Bs[GM_BN][GM_BK + 8];
    int b = blockIdx.z;
    A += (size_t)b * sA;
    B += (size_t)b * sB;
    int m0 = blockIdx.y * GM_BM, n0 = blockIdx.x * GM_BN;
    int tid = threadIdx.x, w = tid >> 5, lane = tid & 31;
    int wm = (w >> 1) * 32, wn = (w & 1) * 32;
    float acc[2][4][4];
    #pragma unroll
    for (int i = 0; i < 2; i++)
        #pragma unroll
        for (int j = 0; j < 4; j++)
            #pragma unroll
            for (int q = 0; q < 4; q++) acc[i][j][q] = 0.f;

    int r8 = lane & 7, grp = lane >> 3;
    for (int k0 = 0; k0 < K; k0 += GM_BK) {
        int rr = tid >> 1, oo = (tid & 1) * 16;
        {
            const __half* pa = A + (size_t)(m0 + rr) * lda + k0 + oo;
            *(uint4*)&As[rr][oo]     = *(const uint4*)pa;
            *(uint4*)&As[rr][oo + 8] = *(const uint4*)(pa + 8);
            const __half* pb = B + (size_t)(n0 + rr) * ldb + k0 + oo;
            *(uint4*)&Bs[rr][oo]     = *(const uint4*)pb;
            *(uint4*)&Bs[rr][oo + 8] = *(const uint4*)(pb + 8);
        }
        __syncthreads();
        #pragma unroll
        for (int kk = 0; kk < GM_BK; kk += 16) {
            unsigned af[2][4], bf[4][2];
            #pragma unroll
            for (int i = 0; i < 2; i++) {
                unsigned ad = sptr(&As[wm + i * 16 + r8 + ((grp & 1) << 3)][kk + ((grp & 2) << 2)]);
                ldsm4(af[i][0], af[i][1], af[i][2], af[i][3], ad);
            }
            #pragma unroll
            for (int jp = 0; jp < 2; jp++) {
                unsigned q0, q1, q2, q3;
                unsigned ad = sptr(&Bs[wn + jp * 16 + r8 + ((grp & 2) << 2)][kk + ((grp & 1) << 3)]);
                ldsm4(q0, q1, q2, q3, ad);
                bf[jp * 2][0] = q0;     bf[jp * 2][1] = q1;
                bf[jp * 2 + 1][0] = q2; bf[jp * 2 + 1][1] = q3;
            }
            #pragma unroll
            for (int i = 0; i < 2; i++)
                #pragma unroll
                for (int j = 0; j < 4; j++) mma16816(acc[i][j], af[i], bf[j]);
        }
        __syncthreads();
    }
    int rr = lane >> 2, cg = (lane & 3) * 2;
    #pragma unroll
    for (int i = 0; i < 2; i++) {
        int gm = m0 + wm + i * 16 + rr;
        #pragma unroll
        for (int j = 0; j < 4; j++) {
            int gn = n0 + wn + j * 8 + cg;
            float bx = bias ? bias[gn] : 0.f;
            float by = bias ? bias[gn + 1] : 0.f;
            float v0 = acc[i][j][0] + bx, v1 = acc[i][j][1] + by;
            float v2 = acc[i][j][2] + bx, v3 = acc[i][j][3] + by;
            if (flags & 1) {
                v0 = fmaxf(v0, 0.f); v1 = fmaxf(v1, 0.f);
                v2 = fmaxf(v2, 0.f); v3 = fmaxf(v3, 0.f);
            }
            if (flags & 4) {                       // transposed fp16 out: C[n][m]
                __half* C = (__half*)Cv + (size_t)b * sC;
                C[(size_t)gn * ldc + gm]           = __float2half(v0);
                C[(size_t)(gn + 1) * ldc + gm]     = __float2half(v1);
                C[(size_t)gn * ldc + gm + 8]       = __float2half(v2);
                C[(size_t)(gn + 1) * ldc + gm + 8] = __float2half(v3);
            } else if (flags & 2) {
                __half* C = (__half*)Cv + (size_t)b * sC;
                *(__half2*)(C + (size_t)gm * ldc + gn) = __floats2half2_rn(v0, v1);
                *(__half2*)(C + (size_t)(gm + 8) * ldc + gn) = __floats2half2_rn(v2, v3);
            } else {
                float* C = (float*)Cv + (size_t)b * sC;
                *(float2*)(C + (size_t)gm * ldc + gn) = make_float2(v0, v1);
                *(float2*)(C + (size_t)(gm + 8) * ldc + gn) = make_float2(v2, v3);
            }
        }
    }
}

// ---------------- adjacency GEMM: h1 = relu(D^-1/2 A D^-1/2 @ p + b1) ----------
// A = uint8 adjacency [NSP][NSP], normalization fused into fp16 staging.
// B = pT [j][s] (ldb=NSP).  M=NSP, N=HID, K=NSP.  fp16 out h1[s][j].
__global__ __launch_bounds__(128) void adj_gemm(
    const float* __restrict__ bias)
{
    __shared__ __half As[GM_BM][GM_BK + 8];
    __shared__ __half Bs[GM_BN][GM_BK + 8];
    __shared__ float sInv[NSP];
    int b = blockIdx.z;
    const unsigned char* A8 = g_adj + (size_t)b * NSP * NSP;
    const __half* B = g_pT + (size_t)b * HID * NSP;
    __half* C = g_h1 + (size_t)b * NSP * HID;
    int m0 = blockIdx.y * GM_BM, n0 = blockIdx.x * GM_BN;
    int tid = threadIdx.x, w = tid >> 5, lane = tid & 31;
    int wm = (w >> 1) * 32, wn = (w & 1) * 32;
    #pragma unroll
    for (int i = 0; i < NSP / 128; i++)
        sInv[tid + i * 128] = g_invdeg[b * NSP + tid + i * 128];
    __syncthreads();

    float acc[2][4][4];
    #pragma unroll
    for (int i = 0; i < 2; i++)
        #pragma unroll
        for (int j = 0; j < 4; j++)
            #pragma unroll
            for (int q = 0; q < 4; q++) acc[i][j][q] = 0.f;

    int r8 = lane & 7, grp = lane >> 3;
    for (int k0 = 0; k0 < NSP; k0 += GM_BK) {
        int rr = tid >> 1, oo = (tid & 1) * 16;
        {
            // A: 16 adjacency bytes -> fp16 with invdeg[m]*invdeg[k]
            float im = sInv[m0 + rr];
            const unsigned* pa = (const unsigned*)(A8 + (size_t)(m0 + rr) * NSP + k0 + oo);
            __half hbuf[16];
            #pragma unroll
            for (int q = 0; q < 4; q++) {
                unsigned v = pa[q];
                #pragma unroll
                for (int e = 0; e < 4; e++) {
                    unsigned byte = (v >> (8 * e)) & 0xffu;
                    int kidx = k0 + oo + q * 4 + e;
                    hbuf[q * 4 + e] = byte ? __float2half(im * sInv[kidx]) : __half(0);
                }
            }
            *(uint4*)&As[rr][oo]     = *(uint4*)&hbuf[0];
            *(uint4*)&As[rr][oo + 8] = *(uint4*)&hbuf[8];
            // B staging (pT rows n = j)
            const __half* pb = B + (size_t)(n0 + rr) * NSP + k0 + oo;
            *(uint4*)&Bs[rr][oo]     = *(const uint4*)pb;
            *(uint4*)&Bs[rr][oo + 8] = *(const uint4*)(pb + 8);
        }
        __syncthreads();
        #pragma unroll
        for (int kk = 0; kk < GM_BK; kk += 16) {
            unsigned af[2][4], bf[4][2];
            #pragma unroll
            for (int i = 0; i < 2; i++) {
                unsigned ad = sptr(&As[wm + i * 16 + r8 + ((grp & 1) << 3)][kk + ((grp & 2) << 2)]);
                ldsm4(af[i][0], af[i][1], af[i][2], af[i][3], ad);
            }
            #pragma unroll
            for (int jp = 0; jp < 2; jp++) {
                unsigned q0, q1, q2, q3;
                unsigned ad = sptr(&Bs[wn + jp * 16 + r8 + ((grp & 2) << 2)][kk + ((grp & 1) << 3)]);
                ldsm4(q0, q1, q2, q3, ad);
                bf[jp * 2][0] = q0;     bf[jp * 2][1] = q1;
                bf[jp * 2 + 1][0] = q2; bf[jp * 2 + 1][1] = q3;
            }
            #pragma unroll
            for (int i = 0; i < 2; i++)
                #pragma unroll
                for (int j = 0; j < 4; j++) mma16816(acc[i][j], af[i], bf[j]);
        }
        __syncthreads();
    }
    int rr = lane >> 2, cg = (lane & 3) * 2;
    #pragma unroll
    for (int i = 0; i < 2; i++) {
        int gm = m0 + wm + i * 16 + rr;
        #pragma unroll
        for (int j = 0; j < 4; j++) {
            int gn = n0 + wn + j * 8 + cg;
            float bx = bias[gn], by = bias[gn + 1];
            float v0 = fmaxf(acc[i][j][0] + bx, 0.f);
            float v1 = fmaxf(acc[i][j][1] + by, 0.f);
            float v2 = fmaxf(acc[i][j][2] + bx, 0.f);
            float v3 = fmaxf(acc[i][j][3] + by, 0.f);
            *(__half2*)(C + (size_t)gm * HID + gn) = __floats2half2_rn(v0, v1);
            *(__half2*)(C + (size_t)(gm + 8) * HID + gn) = __floats2half2_rn(v2, v3);
        }
    }
}

// ---------------- row-normalize z1, z2 (in place) + diag ------------------------
__global__ __launch_bounds__(256) void norm_kernel() {
    int b = blockIdx.y;
    int row = blockIdx.x * 8 + (threadIdx.x >> 5);
    int lane = threadIdx.x & 31;
    float* z1 = g_z1 + ((size_t)b * NSP + row) * ODIM;
    float* z2 = g_z2 + ((size_t)b * NSP + row) * ODIM;
    float a0 = z1[lane], a1 = z1[lane + 32];
    float ss = a0 * a0 + a1 * a1;
    #pragma unroll
    for (int o = 16; o; o >>= 1) ss += __shfl_xor_sync(0xffffffffu, ss, o);
    float inv = rsqrtf(fmaxf(ss, 1e-30f));
    float a0n = a0 * inv, a1n = a1 * inv;
    z1[lane] = a0n; z1[lane + 32] = a1n;
    float c0 = z2[lane], c1 = z2[lane + 32];
    float ss2 = c0 * c0 + c1 * c1;
    #pragma unroll
    for (int o = 16; o; o >>= 1) ss2 += __shfl_xor_sync(0xffffffffu, ss2, o);
    float inv2 = rsqrtf(fmaxf(ss2, 1e-30f));
    float c0n = c0 * inv2, c1n = c1 * inv2;
    z2[lane] = c0n; z2[lane + 32] = c1n;
    float dd = a0n * c0n + a1n * c1n;
    #pragma unroll
    for (int o = 16; o; o >>= 1) dd += __shfl_xor_sync(0xffffffffu, dd, o);
    if (lane == 0) g_diag[b * NSP + row] = dd * INV_T;
}

// ---------------- fused sim GEMM + online logsumexp + loss ---------------------
__global__ __launch_bounds__(256) void simlse_kernel(float* __restrict__ out) {
    __shared__ float As[ODIM][36];
    __shared__ float Bs[ODIM][66];
    __shared__ float sloss[32];
    int b = blockIdx.y;
    int m0 = blockIdx.x * 32;
    int tid = threadIdx.x;
    int tx = tid & 31, ty = tid >> 5;
    const float* z1 = g_z1 + (size_t)b * NSP * ODIM;
    const float* z2 = g_z2 + (size_t)b * NSP * ODIM;
    {
        int r = tid >> 3, cg = (tid & 7) * 8;
        float4 v1 = *(const float4*)(z1 + (size_t)(m0 + r) * ODIM + cg);
        float4 v2 = *(const float4*)(z1 + (size_t)(m0 + r) * ODIM + cg + 4);
        As[cg + 0][r] = v1.x; As[cg + 1][r] = v1.y; As[cg + 2][r] = v1.z; As[cg + 3][r] = v1.w;
        As[cg + 4][r] = v2.x; As[cg + 5][r] = v2.y; As[cg + 6][r] = v2.z; As[cg + 7][r] = v2.w;
    }
    float mrun[4], srun[4];
    #pragma unroll
    for (int i = 0; i < 4; i++) { mrun[i] = -1e30f; srun[i] = 0.f; }

    for (int n0 = 0; n0 < NSP; n0 += 64) {
        __syncthreads();
        {
            int r = tid >> 2, cg = (tid & 3) * 16;
            #pragma unroll
            for (int q = 0; q < 4; q++) {
                float4 v = *(const float4*)(z2 + (size_t)(n0 + r) * ODIM + cg + q * 4);
                Bs[cg + q * 4 + 0][r] = v.x; Bs[cg + q * 4 + 1][r] = v.y;
                Bs[cg + q * 4 + 2][r] = v.z; Bs[cg + q * 4 + 3][r] = v.w;
            }
        }
        __syncthreads();
        float acc[4][2];
        #pragma unroll
        for (int i = 0; i < 4; i++) { acc[i][0] = 0.f; acc[i][1] = 0.f; }
        #pragma unroll
        for (int kk = 0; kk < ODIM; kk++) {
            float4 a = *(const float4*)&As[kk][ty * 4];
            float2 bb = *(const float2*)&Bs[kk][tx * 2];
            float ar[4] = {a.x, a.y, a.z, a.w};
            #pragma unroll
            for (int i = 0; i < 4; i++) {
                acc[i][0] += ar[i] * bb.x;
                acc[i][1] += ar[i] * bb.y;
            }
        }
        #pragma unroll
        for (int i = 0; i < 4; i++) {
            #pragma unroll
            for (int j = 0; j < 2; j++) {
                float v = acc[i][j] * INV_T;
                if (v > mrun[i]) { srun[i] = srun[i] * __expf(mrun[i] - v) + 1.f; mrun[i] = v; }
                else             { srun[i] += __expf(v - mrun[i]); }
            }
        }
    }
    #pragma unroll
    for (int i = 0; i < 4; i++) {
        float m = mrun[i], s = srun[i];
        #pragma unroll
        for (int o = 16; o; o >>= 1) {
            float m2 = __shfl_xor_sync(0xffffffffu, m, o);
            float s2 = __shfl_xor_sync(0xffffffffu, s, o);
            float mn = fmaxf(m, m2);
            s = s * __expf(m - mn) + s2 * __expf(m2 - mn);
            m = mn;
        }
        if (tx == 0) {
            int row = m0 + ty * 4 + i;
            float lse = m + logf(s);
            sloss[ty * 4 + i] = lse - g_diag[b * NSP + row];
        }
    }
    __syncthreads();
    if (tid == 0) {
        float sum = 0.f;
        #pragma unroll
        for (int i = 0; i < 32; i++) sum += sloss[i];
        atomicAdd(out, sum * (1.0f / (NBATCH * NSP)));
    }
}

// ---------------- host launcher -----------------------------------------------
static void* dvp(const void* sym) {
    void* p = nullptr;
    cudaGetSymbolAddress(&p, sym);
    return p;
}

extern "C" void kernel_launch(void* const* d_in, const int* in_sizes, int n_in,
                              void* d_out, int out_size) {
    const float* features = (const float*)d_in[0];
    const int*   spidx    = (const int*)d_in[1];
    const float* W1  = (const float*)d_in[2];
    const float* b1  = (const float*)d_in[3];
    const float* W2  = (const float*)d_in[4];
    const float* b2  = (const float*)d_in[5];
    const float* Wp1 = (const float*)d_in[6];
    const float* bp1 = (const float*)d_in[7];
    const float* Wp2 = (const float*)d_in[8];
    const float* bp2 = (const float*)d_in[9];
    float* out = (float*)d_out;

    __half* p_spfh = (__half*)dvp(g_spfh);
    __half* p_pT   = (__half*)dvp(g_pT);
    __half* p_h1   = (__half*)dvp(g_h1);
    __half* p_h2   = (__half*)dvp(g_h2);
    __half* p_w1h  = (__half*)dvp(g_w1h);
    __half* p_w2h  = (__half*)dvp(g_w2h);
    __half* p_wp1h = (__half*)dvp(g_wp1h);
    __half* p_wp2h = (__half*)dvp(g_wp2h);
    float*  p_z1   = (float*)dvp(g_z1);
    float*  p_z2   = (float*)dvp(g_z2);

    zero_kernel<<<2048, 256>>>(out);
    count_adj_kernel<<<dim3(HW / 1024, NBATCH), 256>>>(spidx);
    scan_kernel<<<NBATCH, 1024>>>();
    invdeg_kernel<<<dim3(NSP / 8, NBATCH), 256>>>();
    cvtw_kernel<<<256, 256>>>(W1, W2, Wp1, Wp2);
    // aggregation: all batches in two launches
    transpose_kernel<<<dim3(HW / 64, NC / 64, NBATCH), 256>>>(features, spidx);
    segsum_kernel<<<dim3(NSP, NBATCH), 128>>>();
    // gemm1: pT[j][s] = (spfh @ W1^T)^T   (transposed fp16 out)
    mma_gemm<<<dim3(HID / GM_BN, NSP / GM_BM, NBATCH), 128>>>(
        p_spfh, NC, (size_t)NSP * NC,
        p_w1h, NC, 0,
        p_pT, NSP, (size_t)HID * NSP,
        NC, nullptr, 4);
    // gemm2: h1 = relu(adj_norm @ p + b1)  — byte-A with fused normalization
    adj_gemm<<<dim3(HID / GM_BN, NSP / GM_BM, NBATCH), 128>>>(b1);
    // gemm3: h2 = relu(h1 @ W2^T + b2)
    mma_gemm<<<dim3(HID / GM_BN, NSP / GM_BM, NBATCH), 128>>>(
        p_h1, HID, (size_t)NSP * HID,
        p_w2h, HID, 0,
        p_h2, HID, (size_t)NSP * HID,
        HID, b2, 3);
    // gemm4: z = h2 @ Wp^T + bp (fp32 out)
    mma_gemm<<<dim3(ODIM / GM_BN, NSP / GM_BM, NBATCH), 128>>>(
        p_h2, HID, (size_t)NSP * HID,
        p_wp1h, HID, 0,
        p_z1, ODIM, (size_t)NSP * ODIM,
        HID, bp1, 0);
    mma_gemm<<<dim3(ODIM / GM_BN, NSP / GM_BM, NBATCH), 128>>>(
        p_h2, HID, (size_t)NSP * HID,
        p_wp2h, HID, 0,
        p_z2, ODIM, (size_t)NSP * ODIM,
        HID, bp2, 0);
    norm_kernel<<<dim3(NSP / 8, NBATCH), 256>>>();
    simlse_kernel<<<dim3(NSP / 32, NBATCH), 256>>>(out);
}